// round 16
// baseline (speedup 1.0000x reference)
#include <cuda_runtime.h>
#include <cuda_fp16.h>
#include <cstdint>

// ======================= problem constants =======================
#define B_    16
#define CIN_  512
#define COUT_ 512
#define H_    64
#define W_    64
#define HW_   4096
#define SDIM_ 512

static __device__ __constant__ float MOD_SCALE_C  = 0.04419417382415922f;   // 1/sqrt(512)
static __device__ __constant__ float CONV_SCALE_C = 0.014731391274719742f;  // 1/sqrt(512*9)

// ======================= device scratch (no allocs allowed) =======================
__device__ float g_s[B_ * CIN_];
__device__ float g_demod[B_ * COUT_];
__device__ float g_wsq[COUT_ * CIN_];   // o-major: wsq[o][ci] = sum_t w[o,ci,t]^2
// f16 scaled input, channel-pair interleaved: word[b][c2][y][x] = {x[2c2], x[2c2+1]} * s * CONV_SCALE
__device__ __align__(16) uint32_t g_xs2[B_ * (CIN_ / 2) * HW_];
// f16 weight taps: [tap][o][ci]
__device__ __align__(16) __half g_wtap[9 * COUT_ * CIN_];

// ======================= helpers =======================
__device__ __forceinline__ uint32_t smem_to_u32(const void* p) {
    uint32_t a;
    asm("{ .reg .u64 t; cvta.to.shared.u64 t, %1; cvt.u32.u64 %0, t; }" : "=r"(a) : "l"(p));
    return a;
}
__device__ __forceinline__ uint32_t pack_half2(float lo, float hi) {
    uint32_t l = (uint32_t)__half_as_ushort(__float2half_rn(lo));
    uint32_t h = (uint32_t)__half_as_ushort(__float2half_rn(hi));
    return l | (h << 16);
}

#define CP16(dst_s, src_g) \
    asm volatile("cp.async.cg.shared.global [%0], [%1], 16;" \
                 :: "r"(dst_s), "l"(src_g) : "memory")
#define CP_COMMIT() asm volatile("cp.async.commit_group;" ::: "memory")
#define CP_WAIT0()  asm volatile("cp.async.wait_group 0;" ::: "memory")

// f16 mma, fp32 accumulate: D(16x8) += A(16x16) * B(16x8)
#define MMA_F16(d, a0, a1, a2, a3, b0, b1)                                   \
    asm volatile("mma.sync.aligned.m16n8k16.row.col.f32.f16.f16.f32 "        \
        "{%0,%1,%2,%3}, {%4,%5,%6,%7}, {%8,%9}, {%0,%1,%2,%3};"              \
        : "+f"((d)[0]), "+f"((d)[1]), "+f"((d)[2]), "+f"((d)[3])             \
        : "r"(a0), "r"(a1), "r"(a2), "r"(a3), "r"(b0), "r"(b1))

// ldmatrix x4: loads 4 8x8 f16 matrices; lane groups 0-7/8-15/16-23/24-31 supply
// the 8 row addresses of matrices 0..3 respectively.
#define LDSM_X4(d0, d1, d2, d3, addr)                                        \
    asm volatile("ldmatrix.sync.aligned.m8n8.x4.shared.b16 {%0,%1,%2,%3}, [%4];" \
        : "=r"(d0), "=r"(d1), "=r"(d2), "=r"(d3) : "r"(addr))

// ======================= prep kernel =======================
// blocks [0,512): o = blk, ci = tid. Reads weight[o,ci,0..9) (warp spans 1152
// contiguous bytes), computes wsq[o][ci] (coalesced write) AND wtap[t][o][ci]
// (coalesced per tap). The old i-major wsq branch (18KB lane stride, 140us) is gone.
// blocks [512,528): modulation s[b,i].
__global__ void __launch_bounds__(512) prep_kernel(const float* __restrict__ style,
                                                   const float* __restrict__ mod_weight,
                                                   const float* __restrict__ mod_bias,
                                                   const float* __restrict__ weight) {
    const int blk = blockIdx.x, tid = threadIdx.x;
    if (blk < 512) {
        const int o = blk, ci = tid;
        const float* w = weight + ((size_t)o * CIN_ + ci) * 9;
        float acc = 0.f;
        float wv[9];
#pragma unroll
        for (int t = 0; t < 9; t++) {
            wv[t] = w[t];
            acc = fmaf(wv[t], wv[t], acc);
        }
        g_wsq[o * CIN_ + ci] = acc;
#pragma unroll
        for (int t = 0; t < 9; t++)
            g_wtap[((size_t)t * COUT_ + o) * CIN_ + ci] = __float2half_rn(wv[t]);
    } else {
        __shared__ float st[SDIM_];
        const int b = blk - 512, i = tid;
        st[i] = style[b * SDIM_ + i];
        __syncthreads();
        const float* wr = mod_weight + (size_t)i * SDIM_;
        float acc = 0.f;
#pragma unroll 8
        for (int j = 0; j < SDIM_; j++) acc = fmaf(st[j], wr[j], acc);
        g_s[b * CIN_ + i] = acc * MOD_SCALE_C + mod_bias[i];
    }
}

// fused: blocks [0,8192) = x -> f16 half2 channel-pair images; [8192,8208) = demod.
// demod thread o reads its own contiguous wsq row (128 float4, L2-resident).
__global__ void __launch_bounds__(512) xs2_demod_kernel(const float* __restrict__ x) {
    if (blockIdx.x < 8192) {
        int idx = blockIdx.x * 512 + threadIdx.x;          // (b, c2, pix4)
        int bc2 = idx >> 10;
        int p4  = (idx & 1023) * 4;
        int b = bc2 >> 8, c2 = bc2 & 255;
        float sc0 = g_s[b * CIN_ + 2 * c2]     * CONV_SCALE_C;
        float sc1 = g_s[b * CIN_ + 2 * c2 + 1] * CONV_SCALE_C;
        const float4 v0 = *(const float4*)(x + ((size_t)(b * CIN_ + 2 * c2))     * HW_ + p4);
        const float4 v1 = *(const float4*)(x + ((size_t)(b * CIN_ + 2 * c2 + 1)) * HW_ + p4);
        uint4 r;
        r.x = pack_half2(v0.x * sc0, v1.x * sc1);
        r.y = pack_half2(v0.y * sc0, v1.y * sc1);
        r.z = pack_half2(v0.z * sc0, v1.z * sc1);
        r.w = pack_half2(v0.w * sc0, v1.w * sc1);
        ((uint4*)g_xs2)[idx] = r;
    } else {
        __shared__ float s2[CIN_];
        int b = blockIdx.x - 8192, o = threadIdx.x;
        float sv = g_s[b * CIN_ + o];
        s2[o] = sv * sv;
        __syncthreads();
        const float4* wr = (const float4*)(g_wsq + o * CIN_);
        float acc = 0.f;
#pragma unroll 8
        for (int i4 = 0; i4 < CIN_ / 4; i4++) {
            float4 w4 = wr[i4];
            acc = fmaf(s2[i4 * 4 + 0], w4.x, acc);
            acc = fmaf(s2[i4 * 4 + 1], w4.y, acc);
            acc = fmaf(s2[i4 * 4 + 2], w4.z, acc);
            acc = fmaf(s2[i4 * 4 + 3], w4.w, acc);
        }
        float cs2 = CONV_SCALE_C * CONV_SCALE_C;
        g_demod[b * COUT_ + o] = rsqrtf(acc * cs2 + 1e-8f);
    }
}

// ======================= main mma.sync f16 conv kernel (unchanged) =======================
// CTA tile: M=128 outch x N=256 px (4 rows of 64). 8 warps (2m x 4n), warp 64x64.
// 16 STAGES of 32 ci; each stage loops 9 taps x 2 k16-steps = 18 fragment steps,
// register double-buffered, no barriers inside a stage. A via ldmatrix.x4
// (XOR chunk-swizzled), B via LDS.32.
#define ATAP_W   2048                    // 128 rows x 16 words
#define ACHUNK_W (9 * ATAP_W)            // 18432
#define BSTAGE_W 7040
#define B0_W     (2 * ACHUNK_W)          // 36864
#define SMEM_W   (2 * ACHUNK_W + 2 * BSTAGE_W)   // 50944 words = 203776 B

__global__ void __launch_bounds__(256, 1)
conv_mma_kernel(float* __restrict__ out) {
    extern __shared__ uint32_t smem[];
    const uint32_t smem_u = smem_to_u32(smem);

    const int tid  = threadIdx.x;
    const int wid  = tid >> 5, lane = tid & 31;
    const int gid  = lane >> 2, tig = lane & 3;
    const int wm   = wid >> 2, wn = wid & 3;      // 2 m-warps x 4 n-warps
    const int nt   = blockIdx.x, mt = blockIdx.y, b = blockIdx.z;
    const int y0   = nt * 4;
    const int m0   = mt * 128;

    // zero both B buffers once: halo cols + y-OOB rows stay zero forever.
    for (int i = tid; i < (2 * BSTAGE_W) / 4; i += 256)
        ((uint4*)(smem + B0_W))[i] = make_uint4(0, 0, 0, 0);
    __syncthreads();

    // -------- cp.async issuers --------
    auto issueA = [&](int c) {   // ci-chunk c: all 9 taps
        const int ci0 = c * 32;
        const uint32_t abase = smem_u + ((c & 1) * ACHUNK_W) * 4;
#pragma unroll
        for (int i = 0; i < 18; i++) {
            int idx = tid + i * 256;             // 4608 x 16B chunks
            int tap = idx >> 9, rem = idx & 511;
            int row = rem >> 2, cg = rem & 3;
            int dstw = tap * ATAP_W + row * 16 + ((cg ^ ((row >> 1) & 3)) << 2);
            CP16(abase + dstw * 4,
                 g_wtap + ((size_t)tap * COUT_ + m0 + row) * CIN_ + ci0 + cg * 8);
        }
    };
    auto issueB = [&](int c) {   // ci-chunk c (32 ci = 16 half2 channels)
        const int c20 = c * 16;
        const uint32_t dst = smem_u + (B0_W + (c & 1) * BSTAGE_W) * 4;
#pragma unroll
        for (int i = 0; i < 6; i++) {
            int idx = tid + i * 256;             // 1536 x 16B chunks
            int c2 = idx / 96, rem = idx % 96;
            int r = rem >> 4, cg = rem & 15;
            int y = y0 - 1 + r;
            if ((unsigned)y < H_)
                CP16(dst + c2 * 1760 + r * 288 + 16 + cg * 16,
                     g_xs2 + (((size_t)(b * (CIN_ / 2) + c20 + c2)) * H_ + y) * W_ + cg * 4);
        }
    };

    float acc[4][8][4];
#pragma unroll
    for (int mf = 0; mf < 4; mf++)
#pragma unroll
        for (int nf = 0; nf < 8; nf++)
#pragma unroll
            for (int k = 0; k < 4; k++) acc[mf][nf][k] = 0.f;

    // -------- per-lane ldmatrix addressing (matrix j = lane>>3, row r = lane&7) --
    const int jj = lane >> 3, rr = lane & 7;
    const int sl = (rr >> 1) & 3;
    const uint32_t a_row_w  = (uint32_t)((wm * 64 + 8 * (jj & 1) + rr) * 16);
    const uint32_t a_cg_w0  = (uint32_t)((((jj >> 1) + 0) ^ sl) << 2);
    const uint32_t a_cg_w1  = (uint32_t)((((jj >> 1) + 2) ^ sl) << 2);

    // fragment double buffers
    uint32_t fa[2][4][4];
    uint32_t fb0[2][8], fb1[2][8];

    const uint32_t* Bbase = smem + B0_W + tig * 440 + gid + 3;

    auto load_step = [&](int c, int step, int p) {
        const int tap = step >> 1, ks = step & 1;
        const int dy = tap / 3, dx = tap % 3;
        const uint32_t abase = smem_u
            + (((c & 1) * ACHUNK_W + tap * ATAP_W + a_row_w
                + (ks ? a_cg_w1 : a_cg_w0)) << 2);
#pragma unroll
        for (int mf = 0; mf < 4; mf++)
            LDSM_X4(fa[p][mf][0], fa[p][mf][1], fa[p][mf][2], fa[p][mf][3],
                    abase + (uint32_t)(mf * 256 * 4));
        const uint32_t* Bw = Bbase + (c & 1) * BSTAGE_W + (wn + dy) * 72 + dx
                             + ks * 3520;
#pragma unroll
        for (int nf = 0; nf < 8; nf++) {
            fb0[p][nf] = Bw[nf * 8];            // c2 = tig
            fb1[p][nf] = Bw[nf * 8 + 1760];     // c2 = tig+4
        }
    };

    // prologue
    issueB(0);
    issueA(0);
    CP_COMMIT();

    for (int c = 0; c < 16; c++) {
        CP_WAIT0();
        __syncthreads();
        if (c + 1 < 16) {
            issueA(c + 1);
            issueB(c + 1);
            CP_COMMIT();
        }

        load_step(c, 0, 0);
#pragma unroll
        for (int step = 0; step < 18; step++) {
            const int p = step & 1;
            if (step + 1 < 18) load_step(c, step + 1, p ^ 1);
#pragma unroll
            for (int mf = 0; mf < 4; mf++)
#pragma unroll
                for (int nf = 0; nf < 8; nf++)
                    MMA_F16(acc[mf][nf], fa[p][mf][0], fa[p][mf][1],
                            fa[p][mf][2], fa[p][mf][3], fb0[p][nf], fb1[p][nf]);
        }
    }

    // -------- epilogue: demodulate + store --------
    const int y = y0 + wn;
#pragma unroll
    for (int mf = 0; mf < 4; mf++) {
        const int o0 = m0 + wm * 64 + mf * 16 + gid;
        const float dmlo = g_demod[b * COUT_ + o0];
        const float dmhi = g_demod[b * COUT_ + o0 + 8];
        float* plo = out + (((size_t)b * COUT_ + o0) * H_ + y) * W_;
        float* phi = plo + 8 * (size_t)HW_;
#pragma unroll
        for (int nf = 0; nf < 8; nf++) {
            const int x = nf * 8 + 2 * tig;
            float2 vlo, vhi;
            vlo.x = acc[mf][nf][0] * dmlo;
            vlo.y = acc[mf][nf][1] * dmlo;
            vhi.x = acc[mf][nf][2] * dmhi;
            vhi.y = acc[mf][nf][3] * dmhi;
            *(float2*)(plo + x) = vlo;
            *(float2*)(phi + x) = vhi;
        }
    }
}

// ======================= host side =======================
extern "C" void kernel_launch(void* const* d_in, const int* in_sizes, int n_in,
                              void* d_out, int out_size) {
    const float* x          = (const float*)d_in[0];
    const float* style      = (const float*)d_in[1];
    const float* weight     = (const float*)d_in[2];
    const float* mod_weight = (const float*)d_in[3];
    const float* mod_bias   = (const float*)d_in[4];
    float* out = (float*)d_out;

    prep_kernel<<<528, 512>>>(style, mod_weight, mod_bias, weight);
    xs2_demod_kernel<<<8208, 512>>>(x);

    static bool configured = false;
    if (!configured) {
        cudaFuncSetAttribute(conv_mma_kernel,
                             cudaFuncAttributeMaxDynamicSharedMemorySize,
                             SMEM_W * 4);
        configured = true;
    }
    dim3 grid(16, 4, B_);   // (n-tiles, m-tiles, batch) = 1024 CTAs
    conv_mma_kernel<<<grid, 256, SMEM_W * 4>>>(out);
}